// round 14
// baseline (speedup 1.0000x reference)
#include <cuda_runtime.h>
#include <math.h>

typedef unsigned long long ull;
typedef unsigned u32;

// ---------------- scratch ----------------
__device__ u32 g_act1[64 * 63 * 63];
__device__ u32 g_act2[64 * 31 * 31 * 2];
__device__ u32 g_w2b[64 * 9];
__device__ u32 g_w3b[128 * 9 * 2];
__device__ int4 g_c2[64];
__device__ int4 g_c3[128];
__device__ char g_act4b[64 * 225 * 128];   // L4 input +-1 s8  [b][pos][ci]
__device__ u32 g_w4f[36 * 32 * 32 * 2];    // L4 B-fragments [ks][nt][lane][2]

#define BN_EPS 1e-3f

// ---------------- f32x2 helpers ----------------
__device__ __forceinline__ ull pack2(float lo, float hi) {
    ull r; asm("mov.b64 %0, {%1, %2};" : "=l"(r) : "f"(lo), "f"(hi)); return r;
}
__device__ __forceinline__ void unpack2(float& lo, float& hi, ull v) {
    asm("mov.b64 {%0, %1}, %2;" : "=f"(lo), "=f"(hi) : "l"(v));
}
__device__ __forceinline__ ull ffma2(ull a, ull b, ull c) {
    ull d; asm("fma.rn.f32x2 %0, %1, %2, %3;" : "=l"(d) : "l"(a), "l"(b), "l"(c)); return d;
}

// ---------------- s8 mma.sync (m16n8k32, row.col, s32 accum) ----------------
__device__ __forceinline__ void mma_s8(int* d, u32 a0, u32 a1, u32 a2, u32 a3,
                                       u32 b0, u32 b1) {
    asm volatile(
        "mma.sync.aligned.m16n8k32.row.col.s32.s8.s8.s32 "
        "{%0,%1,%2,%3}, {%4,%5,%6,%7}, {%8,%9}, {%0,%1,%2,%3};"
        : "+r"(d[0]), "+r"(d[1]), "+r"(d[2]), "+r"(d[3])
        : "r"(a0), "r"(a1), "r"(a2), "r"(a3), "r"(b0), "r"(b1));
}

// ---------------- CSA popcount ----------------
__device__ __forceinline__ void CSA(u32& s, u32& c, u32 a, u32 b, u32 d) {
    u32 t = a ^ b;
    s = t ^ d;
    c = (a & b) | (t & d);
}
__device__ __forceinline__ int R9(u32 x0, u32 x1, u32 x2, u32 x3, u32 x4,
                                  u32 x5, u32 x6, u32 x7, u32 x8) {
    u32 s0, c0, s1, c1, s2, c2, s3, c3, s4, c4;
    CSA(s0, c0, x0, x1, x2); CSA(s1, c1, x3, x4, x5); CSA(s2, c2, x6, x7, x8);
    CSA(s3, c3, s0, s1, s2); CSA(s4, c4, c0, c1, c2);
    u32 s5 = s4 ^ c3, c5 = s4 & c3;
    u32 s6 = c4 ^ c5, c6 = c4 & c5;
    return __popc(s3) + 2 * __popc(s5) + 4 * __popc(s6) + 8 * __popc(c6);
}
__device__ __forceinline__ int R18(const u32 x[18]) {
    u32 a0, b0, a1, b1, a2, b2, a3, b3, a4, b4, a5, b5;
    CSA(a0, b0, x[0], x[1], x[2]); CSA(a1, b1, x[3], x[4], x[5]); CSA(a2, b2, x[6], x[7], x[8]);
    CSA(a3, b3, x[9], x[10], x[11]); CSA(a4, b4, x[12], x[13], x[14]); CSA(a5, b5, x[15], x[16], x[17]);
    u32 t0, d0, t1, d1;
    CSA(t0, d0, a0, a1, a2); CSA(t1, d1, a3, a4, a5);
    u32 u0 = t0 ^ t1, e0 = t0 & t1;
    return __popc(u0) + 2 * R9(b0, b1, b2, b3, b4, b5, d0, d1, e0);
}
template <int DY, int DX>
__device__ __forceinline__ int win18(const uint2 (&a)[4][4], const uint2 (&w)[9]) {
    u32 x[18];
    #pragma unroll
    for (int kh = 0; kh < 3; kh++)
        #pragma unroll
        for (int kw = 0; kw < 3; kw++) {
            int t = kh * 3 + kw;
            x[2 * t] = a[DY + kh][DX + kw].x ^ w[t].x;
            x[2 * t + 1] = a[DY + kh][DX + kw].y ^ w[t].y;
        }
    return R18(x);
}

// ---------------- pack ----------------
__device__ void do_pack(int i,
                        const float* __restrict__ w2, const float* __restrict__ w3,
                        const float* __restrict__ w4,
                        const float* __restrict__ m2, const float* __restrict__ v2,
                        const float* __restrict__ b2,
                        const float* __restrict__ m3, const float* __restrict__ v3,
                        const float* __restrict__ b3) {
    if (i < 576) {
        int co = i / 9, t = i % 9;
        u32 bits = 0;
        #pragma unroll
        for (int ci = 0; ci < 32; ci++)
            bits |= ((u32)(w2[(t * 32 + ci) * 64 + co] >= 0.f)) << ci;
        g_w2b[co * 9 + t] = bits;
    } else if (i < 2880) {
        int j = i - 576;
        int co = j / 18, r = j % 18, t = r / 2, wd = r % 2;
        u32 bits = 0;
        #pragma unroll
        for (int k = 0; k < 32; k++)
            bits |= ((u32)(w3[(t * 64 + wd * 32 + k) * 128 + co] >= 0.f)) << k;
        g_w3b[(co * 9 + t) * 2 + wd] = bits;
    } else if (i < 2944) {
        int co = i - 2880;
        int ct[9];
        #pragma unroll
        for (int t = 0; t < 9; t++) {
            int pc = 0;
            for (int ci = 0; ci < 32; ci++) pc += (w2[(t * 32 + ci) * 64 + co] >= 0.f);
            ct[t] = 32 - 2 * pc;
        }
        float thr = m2[co] - b2[co] * sqrtf(v2[co] + BN_EPS);
        g_c2[co] = make_int4((int)ceilf(thr), ct[0] + ct[1] + ct[2], ct[0] + ct[3] + ct[6], ct[0]);
    } else if (i < 3072) {
        int co = i - 2944;
        int ct[9];
        #pragma unroll
        for (int t = 0; t < 9; t++) {
            int pc = 0;
            for (int ci = 0; ci < 64; ci++) pc += (w3[(t * 64 + ci) * 128 + co] >= 0.f);
            ct[t] = 64 - 2 * pc;
        }
        float thr = m3[co] - b3[co] * sqrtf(v3[co] + BN_EPS);
        g_c3[co] = make_int4((int)ceilf(thr), ct[0] + ct[1] + ct[2], ct[0] + ct[3] + ct[6], ct[0]);
    }
    // layer4 B fragments: [ks(36)][nt(32)][lane(32)][reg(2)], tap = ks/4, cq = ks%4
    for (int j = i; j < 73728; j += 12800) {
        int reg = j & 1, lane = (j >> 1) & 31, nt = (j >> 6) & 31, ks = j >> 11;
        int tap = ks >> 2, cq = ks & 3;
        int g = lane >> 2, t = lane & 3;
        int co = nt * 8 + g;
        u32 v = 0;
        #pragma unroll
        for (int e = 0; e < 4; e++) {
            int ci = cq * 32 + reg * 16 + t * 4 + e;
            u32 s8 = (w4[(tap * 128 + ci) * 256 + co] >= 0.f) ? 0x01u : 0xFFu;
            v |= s8 << (8 * e);
        }
        g_w4f[j] = v;
    }
}

#define NB1 993
#define NBP 50

// ---------------- layer 1 (+pack): fp32 conv + maxpool + BN-sign ----------------
__global__ __launch_bounds__(256) void k_layer1(
        const float* __restrict__ x, const float* __restrict__ w1,
        const float* __restrict__ m1, const float* __restrict__ v1,
        const float* __restrict__ b1,
        const float* __restrict__ w2, const float* __restrict__ w3,
        const float* __restrict__ w4,
        const float* __restrict__ m2, const float* __restrict__ v2,
        const float* __restrict__ b2,
        const float* __restrict__ m3, const float* __restrict__ v3,
        const float* __restrict__ b3) {
    int tid = threadIdx.x;
    if (blockIdx.x >= NB1) {
        do_pack((blockIdx.x - NB1) * 256 + tid, w2, w3, w4, m2, v2, b2, m3, v3, b3);
        return;
    }
    __shared__ alignas(16) ull sw2[32 * 28];
    __shared__ float thr[32];
    for (int i = tid; i < 864; i += 256) {
        float s = (w1[i] >= 0.f) ? 1.f : -1.f;
        sw2[(i & 31) * 28 + (i >> 5)] = pack2(s, s);
    }
    if (tid < 32) thr[tid] = m1[tid] - b1[tid] * sqrtf(v1[tid] + BN_EPS);
    __syncthreads();

    int idx = blockIdx.x * 256 + tid;
    if (idx >= 64 * 63 * 63) return;
    int b = idx / 3969, r = idx % 3969;
    int ph = r / 63, pw = r % 63;

    ull xa[4][9];
    const float* xb = x + (size_t)b * 128 * 128 * 3;
    #pragma unroll
    for (int i = 0; i < 4; i++) {
        const float* row = xb + ((2 * ph + i) * 128 + 2 * pw) * 3;
        float f[12];
        #pragma unroll
        for (int j = 0; j < 6; j++) {
            float2 t2 = __ldg((const float2*)row + j);
            f[2 * j] = t2.x; f[2 * j + 1] = t2.y;
        }
        #pragma unroll
        for (int kw = 0; kw < 3; kw++)
            #pragma unroll
            for (int c = 0; c < 3; c++)
                xa[i][kw * 3 + c] = pack2(f[kw * 3 + c], f[kw * 3 + c + 3]);
    }

    u32 word = 0;
    #pragma unroll 2
    for (int co = 0; co < 32; co++) {
        const ulonglong2* wr = (const ulonglong2*)(&sw2[co * 28]);
        ull acc0 = 0ull, acc1 = 0ull;
        #pragma unroll
        for (int kp = 0; kp < 13; kp++) {
            ulonglong2 wp = wr[kp];
            const int k0 = 2 * kp, k1 = 2 * kp + 1;
            acc0 = ffma2(wp.x, xa[k0 / 9][k0 % 9], acc0);
            acc1 = ffma2(wp.x, xa[k0 / 9 + 1][k0 % 9], acc1);
            acc0 = ffma2(wp.y, xa[k1 / 9][k1 % 9], acc0);
            acc1 = ffma2(wp.y, xa[k1 / 9 + 1][k1 % 9], acc1);
        }
        ull w26 = sw2[co * 28 + 26];
        acc0 = ffma2(w26, xa[2][8], acc0);
        acc1 = ffma2(w26, xa[3][8], acc1);
        float a0, a1, a2, a3;
        unpack2(a0, a1, acc0);
        unpack2(a2, a3, acc1);
        word |= ((u32)(fmaxf(fmaxf(a0, a1), fmaxf(a2, a3)) >= thr[co])) << co;
    }
    g_act1[idx] = word;
}

// ---------------- layer 2 ----------------
__device__ __forceinline__ int w9f(const u32 (&a)[4][4], const u32 (&w)[9], int dy, int dx) {
    return R9(a[dy][dx] ^ w[0], a[dy][dx + 1] ^ w[1], a[dy][dx + 2] ^ w[2],
              a[dy + 1][dx] ^ w[3], a[dy + 1][dx + 1] ^ w[4], a[dy + 1][dx + 2] ^ w[5],
              a[dy + 2][dx] ^ w[6], a[dy + 2][dx + 1] ^ w[7], a[dy + 2][dx + 2] ^ w[8]);
}
__global__ __launch_bounds__(256) void k_layer2() {
    int gt = blockIdx.x * 256 + threadIdx.x;
    int gw = gt >> 5, lane = gt & 31;
    int seg = gw & 7, bp = gw >> 3;
    int b = bp / 31, ph = bp % 31;
    int pw0 = seg * 4;

    u32 wA[9], wB[9];
    #pragma unroll
    for (int t = 0; t < 9; t++) {
        wA[t] = g_w2b[lane * 9 + t];
        wB[t] = g_w2b[(lane + 32) * 9 + t];
    }
    int4 cA = g_c2[lane], cB = g_c2[lane + 32];
    int pthrA = (288 - cA.x) >> 1, pthrB = (288 - cB.x) >> 1;

    const u32* rbase = g_act1 + b * 3969 + (2 * ph - 1) * 63;
    bool rv0 = (ph > 0), cv0 = (pw0 > 0);

    u32 a[4][4];
    #pragma unroll
    for (int i = 0; i < 4; i++) {
        bool rv = (i > 0) || rv0;
        #pragma unroll
        for (int j = 0; j < 4; j++) {
            bool cv = (j > 0) || cv0;
            a[i][j] = (rv && cv) ? rbase[i * 63 + 2 * pw0 - 1 + j] : 0u;
        }
    }
    int pbase = b * 961 + ph * 31;

    #pragma unroll
    for (int k = 0; k < 4; k++) {
        int pw = pw0 + k;
        if (pw < 31) {
            int PA[4], PB[4];
            #pragma unroll
            for (int dy = 0; dy < 2; dy++)
                #pragma unroll
                for (int dx = 0; dx < 2; dx++) {
                    PA[dy * 2 + dx] = w9f(a, wA, dy, dx);
                    PB[dy * 2 + dx] = w9f(a, wB, dy, dx);
                }
            bool bitA, bitB;
            if (k == 0 && !(rv0 && cv0)) {
                int cTA = rv0 ? 0 : cA.y, cLA = cv0 ? 0 : cA.z, c0A = (!rv0 && !cv0) ? cA.w : 0;
                int cTB = rv0 ? 0 : cB.y, cLB = cv0 ? 0 : cB.z, c0B = (!rv0 && !cv0) ? cB.w : 0;
                bitA = max(max(288 - 2 * PA[0] - (cTA + cLA - c0A), 288 - 2 * PA[1] - cTA),
                           max(288 - 2 * PA[2] - cLA, 288 - 2 * PA[3])) >= cA.x;
                bitB = max(max(288 - 2 * PB[0] - (cTB + cLB - c0B), 288 - 2 * PB[1] - cTB),
                           max(288 - 2 * PB[2] - cLB, 288 - 2 * PB[3])) >= cB.x;
            } else if (!rv0) {
                bitA = max(max(288 - 2 * PA[0] - cA.y, 288 - 2 * PA[1] - cA.y),
                           max(288 - 2 * PA[2], 288 - 2 * PA[3])) >= cA.x;
                bitB = max(max(288 - 2 * PB[0] - cB.y, 288 - 2 * PB[1] - cB.y),
                           max(288 - 2 * PB[2], 288 - 2 * PB[3])) >= cB.x;
            } else {
                bitA = min(min(PA[0], PA[1]), min(PA[2], PA[3])) <= pthrA;
                bitB = min(min(PB[0], PB[1]), min(PB[2], PB[3])) <= pthrB;
            }
            u32 wordA = __ballot_sync(0xffffffffu, bitA);
            u32 wordB = __ballot_sync(0xffffffffu, bitB);
            if (lane == 0) ((uint2*)g_act2)[pbase + pw] = make_uint2(wordA, wordB);

            if (k < 3 && pw < 30) {
                #pragma unroll
                for (int i = 0; i < 4; i++) {
                    bool rv = (i > 0) || rv0;
                    a[i][0] = a[i][2]; a[i][1] = a[i][3];
                    a[i][2] = rv ? rbase[i * 63 + 2 * pw + 3] : 0u;
                    a[i][3] = rv ? rbase[i * 63 + 2 * pw + 4] : 0u;
                }
            }
        }
    }
}

// ---------------- layer 3: writes s8 activations for L4 MMA ----------------------
__global__ __launch_bounds__(256) void k_layer3() {
    int gt = blockIdx.x * 256 + threadIdx.x;
    int gw = gt >> 5, lane = gt & 31;
    int cow = gw & 3;
    int t1 = gw >> 2;
    int seg = t1 & 3, bp = t1 >> 2;
    int b = bp / 15, ph = bp % 15;
    int co = cow * 32 + lane;
    int pw0 = seg * 4;

    uint2 w[9];
    #pragma unroll
    for (int t = 0; t < 9; t++) w[t] = ((const uint2*)g_w3b)[co * 9 + t];
    int4 c = g_c3[co];
    int pthr = (576 - c.x) >> 1;

    const uint2* rbase = (const uint2*)g_act2 + b * 961 + (2 * ph - 1) * 31;
    bool rv0 = (ph > 0), cv0 = (pw0 > 0);
    uint2 z = make_uint2(0u, 0u);

    uint2 a[4][4];
    #pragma unroll
    for (int i = 0; i < 4; i++) {
        bool rv = (i > 0) || rv0;
        #pragma unroll
        for (int j = 0; j < 4; j++) {
            bool cv = (j > 0) || cv0;
            a[i][j] = (rv && cv) ? rbase[i * 31 + 2 * pw0 - 1 + j] : z;
        }
    }
    char* outb = g_act4b + (size_t)(b * 225 + ph * 15) * 128 + co;

    #pragma unroll
    for (int k = 0; k < 4; k++) {
        int pw = pw0 + k;
        if (pw < 15) {
            int P0 = win18<0, 0>(a, w), P1 = win18<0, 1>(a, w);
            int P2 = win18<1, 0>(a, w), P3 = win18<1, 1>(a, w);
            bool bit;
            if (k == 0 && !(rv0 && cv0)) {
                int cT = rv0 ? 0 : c.y, cL = cv0 ? 0 : c.z, c0 = (!rv0 && !cv0) ? c.w : 0;
                bit = max(max(576 - 2 * P0 - (cT + cL - c0), 576 - 2 * P1 - cT),
                          max(576 - 2 * P2 - cL, 576 - 2 * P3)) >= c.x;
            } else if (!rv0) {
                bit = max(max(576 - 2 * P0 - c.y, 576 - 2 * P1 - c.y),
                          max(576 - 2 * P2, 576 - 2 * P3)) >= c.x;
            } else {
                bit = min(min(P0, P1), min(P2, P3)) <= pthr;
            }
            outb[(size_t)pw * 128] = bit ? (char)1 : (char)-1;

            if (k < 3 && pw < 14) {
                #pragma unroll
                for (int i = 0; i < 4; i++) {
                    bool rv = (i > 0) || rv0;
                    a[i][0] = a[i][2]; a[i][1] = a[i][3];
                    a[i][2] = rv ? rbase[i * 31 + 2 * pw + 3] : z;
                    a[i][3] = rv ? rbase[i * 31 + 2 * pw + 4] : z;
                }
            }
        }
    }
}

// ---------------- layer 4: s8 mma.sync im2col GEMM + pool + BN -------------------
// CTA = (image b, M-half h): 512 thr / 16 warps; warp = n16 column; M-half = 7|6 m16 tiles
#define SM_ACT  0
#define SM_D    28928                      // Dbuf: 112 rows x 264 ints
#define SM_TOT  (28928 + 112 * 264 * 4)    // 147200

__global__ __launch_bounds__(512) void k_l4mma(
        const float* __restrict__ m4, const float* __restrict__ v4,
        const float* __restrict__ b4, float* __restrict__ out) {
    extern __shared__ char dsm[];
    char* actS = dsm + SM_ACT;
    int* Dbuf = (int*)(dsm + SM_D);
    int tid = threadIdx.x;
    int warp = tid >> 5, lane = tid & 31;
    int g = lane >> 2, t = lane & 3;
    int b = blockIdx.x >> 1, h = blockIdx.x & 1;
    int mbase = h ? 112 : 0;
    int NT = h ? 6 : 7;

    // stage activation image (225 x 128 s8 = 28800 B)
    {
        const uint4* src = (const uint4*)(g_act4b + (size_t)b * 28800);
        uint4* dst = (uint4*)actS;
        for (int u = tid; u < 1800; u += 512) dst[u] = src[u];
    }
    __syncthreads();

    // per-warp row metadata: addr | flags (r==0, c==0, valid)
    int meta[7][2];
    #pragma unroll
    for (int mt = 0; mt < 7; mt++)
        #pragma unroll
        for (int hf = 0; hf < 2; hf++) {
            int p = mbase + mt * 16 + g + hf * 8;
            bool pv = (mt < NT) && (p < 196);
            int r = pv ? p / 14 : 0;
            int c = pv ? p % 14 : 0;
            meta[mt][hf] = ((r * 15 + c) * 128 + t * 4)
                         | ((r == 0) ? (1 << 20) : 0)
                         | ((c == 0) ? (1 << 21) : 0)
                         | (pv ? (1 << 22) : 0);
        }

    int acc[7][2][4];
    #pragma unroll
    for (int mt = 0; mt < 7; mt++)
        #pragma unroll
        for (int n = 0; n < 2; n++)
            #pragma unroll
            for (int q = 0; q < 4; q++) acc[mt][n][q] = 0;

    #pragma unroll 1
    for (int ks = 0; ks < 36; ks++) {
        int tap = ks >> 2, cq = ks & 3;
        int kh = tap / 3, kw = tap % 3;
        int koff = ((kh - 1) * 15 + (kw - 1)) * 128 + cq * 32;
        bool iTop = (kh == 0), iLeft = (kw == 0);

        const uint2* wf = (const uint2*)g_w4f + ((ks * 32 + 2 * warp) * 32 + lane);
        uint2 B0 = __ldg(wf);
        uint2 B1 = __ldg(wf + 32);

        #pragma unroll 7
        for (int mt = 0; mt < 7; mt++) {
            if (mt >= NT) break;
            u32 av[4];
            #pragma unroll
            for (int hf = 0; hf < 2; hf++) {
                int m = meta[mt][hf];
                bool ok = (m & (1 << 22))
                        && !((m & (1 << 20)) && iTop)
                        && !((m & (1 << 21)) && iLeft);
                u32 lo = 0, hi = 0;
                if (ok) {
                    const char* ap = actS + (m & 0xFFFFF) + koff;
                    lo = *(const u32*)ap;
                    hi = *(const u32*)(ap + 16);
                }
                av[hf] = lo;
                av[hf + 2] = hi;
            }
            mma_s8(acc[mt][0], av[0], av[1], av[2], av[3], B0.x, B0.y);
            mma_s8(acc[mt][1], av[0], av[1], av[2], av[3], B1.x, B1.y);
        }
    }

    // store D tiles to smem (local rows 0..111 for h=0, 0..95 for h=1)
    #pragma unroll
    for (int mt = 0; mt < 7; mt++) {
        if (mt >= NT) break;
        #pragma unroll
        for (int n = 0; n < 2; n++) {
            int col = warp * 16 + n * 8 + t * 2;
            int r0 = mt * 16 + g, r1 = r0 + 8;
            Dbuf[r0 * 264 + col] = acc[mt][n][0];
            Dbuf[r0 * 264 + col + 1] = acc[mt][n][1];
            Dbuf[r1 * 264 + col] = acc[mt][n][2];
            Dbuf[r1 * 264 + col + 1] = acc[mt][n][3];
        }
    }
    __syncthreads();

    // pool 2x2 + BN
    int npr = h ? 3 : 4, ph0 = h ? 4 : 0;
    int nout = npr * 7 * 256;
    for (int idx = tid; idx < nout; idx += 512) {
        int co = idx & 255, rest = idx >> 8;
        int pw = rest % 7, lp = rest / 7;
        int ph = ph0 + lp;
        int l = (2 * ph) * 14 + 2 * pw - mbase;
        int v0 = Dbuf[l * 264 + co], v1 = Dbuf[(l + 1) * 264 + co];
        int v2 = Dbuf[(l + 14) * 264 + co], v3 = Dbuf[(l + 15) * 264 + co];
        int best = max(max(v0, v1), max(v2, v3));
        out[(size_t)(b * 49 + ph * 7 + pw) * 256 + co] =
            ((float)best - __ldg(m4 + co)) * rsqrtf(__ldg(v4 + co) + BN_EPS) + __ldg(b4 + co);
    }
}

// ---------------- launch ----------------
extern "C" void kernel_launch(void* const* d_in, const int* in_sizes, int n_in,
                              void* d_out, int out_size) {
    const float* x  = (const float*)d_in[0];
    const float* w1 = (const float*)d_in[1];
    const float* m1 = (const float*)d_in[2];
    const float* v1 = (const float*)d_in[3];
    const float* b1 = (const float*)d_in[4];
    const float* w2 = (const float*)d_in[5];
    const float* m2 = (const float*)d_in[6];
    const float* v2 = (const float*)d_in[7];
    const float* b2 = (const float*)d_in[8];
    const float* w3 = (const float*)d_in[9];
    const float* m3 = (const float*)d_in[10];
    const float* v3 = (const float*)d_in[11];
    const float* b3 = (const float*)d_in[12];
    const float* w4 = (const float*)d_in[13];
    const float* m4 = (const float*)d_in[14];
    const float* v4 = (const float*)d_in[15];
    const float* b4 = (const float*)d_in[16];
    float* out = (float*)d_out;

    cudaFuncSetAttribute(k_l4mma, cudaFuncAttributeMaxDynamicSharedMemorySize, SM_TOT);

    k_layer1<<<NB1 + NBP, 256>>>(x, w1, m1, v1, b1, w2, w3, w4, m2, v2, b2, m3, v3, b3);
    k_layer2<<<64 * 31 * 8 * 32 / 256, 256>>>();
    k_layer3<<<64 * 15 * 4 * 4 * 32 / 256, 256>>>();
    k_l4mma<<<128, 512, SM_TOT>>>(m4, v4, b4, out);
}

// round 15
// speedup vs baseline: 1.7285x; 1.7285x over previous
#include <cuda_runtime.h>
#include <math.h>

typedef unsigned long long ull;
typedef unsigned u32;

// ---------------- scratch ----------------
__device__ u32 g_act1[64 * 63 * 63];
__device__ u32 g_act2[64 * 31 * 31 * 2];
__device__ u32 g_w2b[64 * 9];
__device__ u32 g_w3b[128 * 9 * 2];
__device__ int4 g_c2[64];
__device__ int4 g_c3[128];
__device__ char g_act4b[64 * 225 * 128];   // L4 input +-1 s8  [b][pos][ci]
__device__ u32 g_w4f[36 * 32 * 32 * 2];    // L4 B-fragments [ks][nt][lane][2]

#define BN_EPS 1e-3f

// ---------------- f32x2 helpers ----------------
__device__ __forceinline__ ull pack2(float lo, float hi) {
    ull r; asm("mov.b64 %0, {%1, %2};" : "=l"(r) : "f"(lo), "f"(hi)); return r;
}
__device__ __forceinline__ void unpack2(float& lo, float& hi, ull v) {
    asm("mov.b64 {%0, %1}, %2;" : "=f"(lo), "=f"(hi) : "l"(v));
}
__device__ __forceinline__ ull ffma2(ull a, ull b, ull c) {
    ull d; asm("fma.rn.f32x2 %0, %1, %2, %3;" : "=l"(d) : "l"(a), "l"(b), "l"(c)); return d;
}

// ---------------- s8 mma.sync (m16n8k32, row.col, s32 accum) ----------------
__device__ __forceinline__ void mma_s8(int* d, u32 a0, u32 a1, u32 a2, u32 a3,
                                       u32 b0, u32 b1) {
    asm volatile(
        "mma.sync.aligned.m16n8k32.row.col.s32.s8.s8.s32 "
        "{%0,%1,%2,%3}, {%4,%5,%6,%7}, {%8,%9}, {%0,%1,%2,%3};"
        : "+r"(d[0]), "+r"(d[1]), "+r"(d[2]), "+r"(d[3])
        : "r"(a0), "r"(a1), "r"(a2), "r"(a3), "r"(b0), "r"(b1));
}

// ---------------- CSA popcount ----------------
__device__ __forceinline__ void CSA(u32& s, u32& c, u32 a, u32 b, u32 d) {
    u32 t = a ^ b;
    s = t ^ d;
    c = (a & b) | (t & d);
}
__device__ __forceinline__ int R9(u32 x0, u32 x1, u32 x2, u32 x3, u32 x4,
                                  u32 x5, u32 x6, u32 x7, u32 x8) {
    u32 s0, c0, s1, c1, s2, c2, s3, c3, s4, c4;
    CSA(s0, c0, x0, x1, x2); CSA(s1, c1, x3, x4, x5); CSA(s2, c2, x6, x7, x8);
    CSA(s3, c3, s0, s1, s2); CSA(s4, c4, c0, c1, c2);
    u32 s5 = s4 ^ c3, c5 = s4 & c3;
    u32 s6 = c4 ^ c5, c6 = c4 & c5;
    return __popc(s3) + 2 * __popc(s5) + 4 * __popc(s6) + 8 * __popc(c6);
}
__device__ __forceinline__ int R18(const u32 x[18]) {
    u32 a0, b0, a1, b1, a2, b2, a3, b3, a4, b4, a5, b5;
    CSA(a0, b0, x[0], x[1], x[2]); CSA(a1, b1, x[3], x[4], x[5]); CSA(a2, b2, x[6], x[7], x[8]);
    CSA(a3, b3, x[9], x[10], x[11]); CSA(a4, b4, x[12], x[13], x[14]); CSA(a5, b5, x[15], x[16], x[17]);
    u32 t0, d0, t1, d1;
    CSA(t0, d0, a0, a1, a2); CSA(t1, d1, a3, a4, a5);
    u32 u0 = t0 ^ t1, e0 = t0 & t1;
    return __popc(u0) + 2 * R9(b0, b1, b2, b3, b4, b5, d0, d1, e0);
}
template <int DY, int DX>
__device__ __forceinline__ int win18(const uint2 (&a)[4][4], const uint2 (&w)[9]) {
    u32 x[18];
    #pragma unroll
    for (int kh = 0; kh < 3; kh++)
        #pragma unroll
        for (int kw = 0; kw < 3; kw++) {
            int t = kh * 3 + kw;
            x[2 * t] = a[DY + kh][DX + kw].x ^ w[t].x;
            x[2 * t + 1] = a[DY + kh][DX + kw].y ^ w[t].y;
        }
    return R18(x);
}

// ---------------- pack ----------------
__device__ void do_pack(int i,
                        const float* __restrict__ w2, const float* __restrict__ w3,
                        const float* __restrict__ w4,
                        const float* __restrict__ m2, const float* __restrict__ v2,
                        const float* __restrict__ b2,
                        const float* __restrict__ m3, const float* __restrict__ v3,
                        const float* __restrict__ b3) {
    if (i < 576) {
        int co = i / 9, t = i % 9;
        u32 bits = 0;
        #pragma unroll
        for (int ci = 0; ci < 32; ci++)
            bits |= ((u32)(w2[(t * 32 + ci) * 64 + co] >= 0.f)) << ci;
        g_w2b[co * 9 + t] = bits;
    } else if (i < 2880) {
        int j = i - 576;
        int co = j / 18, r = j % 18, t = r / 2, wd = r % 2;
        u32 bits = 0;
        #pragma unroll
        for (int k = 0; k < 32; k++)
            bits |= ((u32)(w3[(t * 64 + wd * 32 + k) * 128 + co] >= 0.f)) << k;
        g_w3b[(co * 9 + t) * 2 + wd] = bits;
    } else if (i < 2944) {
        int co = i - 2880;
        int ct[9];
        #pragma unroll
        for (int t = 0; t < 9; t++) {
            int pc = 0;
            for (int ci = 0; ci < 32; ci++) pc += (w2[(t * 32 + ci) * 64 + co] >= 0.f);
            ct[t] = 32 - 2 * pc;
        }
        float thr = m2[co] - b2[co] * sqrtf(v2[co] + BN_EPS);
        g_c2[co] = make_int4((int)ceilf(thr), ct[0] + ct[1] + ct[2], ct[0] + ct[3] + ct[6], ct[0]);
    } else if (i < 3072) {
        int co = i - 2944;
        int ct[9];
        #pragma unroll
        for (int t = 0; t < 9; t++) {
            int pc = 0;
            for (int ci = 0; ci < 64; ci++) pc += (w3[(t * 64 + ci) * 128 + co] >= 0.f);
            ct[t] = 64 - 2 * pc;
        }
        float thr = m3[co] - b3[co] * sqrtf(v3[co] + BN_EPS);
        g_c3[co] = make_int4((int)ceilf(thr), ct[0] + ct[1] + ct[2], ct[0] + ct[3] + ct[6], ct[0]);
    }
    // layer4 B fragments: [ks(36)][nt(32)][lane(32)][reg(2)]
    for (int j = i; j < 73728; j += 12800) {
        int reg = j & 1, lane = (j >> 1) & 31, nt = (j >> 6) & 31, ks = j >> 11;
        int tap = ks >> 2, cq = ks & 3;
        int g = lane >> 2, t = lane & 3;
        int co = nt * 8 + g;
        u32 v = 0;
        #pragma unroll
        for (int e = 0; e < 4; e++) {
            int ci = cq * 32 + reg * 16 + t * 4 + e;
            u32 s8 = (w4[(tap * 128 + ci) * 256 + co] >= 0.f) ? 0x01u : 0xFFu;
            v |= s8 << (8 * e);
        }
        g_w4f[j] = v;
    }
}

#define NB1 993
#define NBP 50

// ---------------- layer 1 (+pack): fp32 conv + maxpool + BN-sign ----------------
__global__ __launch_bounds__(256) void k_layer1(
        const float* __restrict__ x, const float* __restrict__ w1,
        const float* __restrict__ m1, const float* __restrict__ v1,
        const float* __restrict__ b1,
        const float* __restrict__ w2, const float* __restrict__ w3,
        const float* __restrict__ w4,
        const float* __restrict__ m2, const float* __restrict__ v2,
        const float* __restrict__ b2,
        const float* __restrict__ m3, const float* __restrict__ v3,
        const float* __restrict__ b3) {
    int tid = threadIdx.x;
    if (blockIdx.x >= NB1) {
        do_pack((blockIdx.x - NB1) * 256 + tid, w2, w3, w4, m2, v2, b2, m3, v3, b3);
        return;
    }
    __shared__ alignas(16) ull sw2[32 * 28];
    __shared__ float thr[32];
    for (int i = tid; i < 864; i += 256) {
        float s = (w1[i] >= 0.f) ? 1.f : -1.f;
        sw2[(i & 31) * 28 + (i >> 5)] = pack2(s, s);
    }
    if (tid < 32) thr[tid] = m1[tid] - b1[tid] * sqrtf(v1[tid] + BN_EPS);
    __syncthreads();

    int idx = blockIdx.x * 256 + tid;
    if (idx >= 64 * 63 * 63) return;
    int b = idx / 3969, r = idx % 3969;
    int ph = r / 63, pw = r % 63;

    ull xa[4][9];
    const float* xb = x + (size_t)b * 128 * 128 * 3;
    #pragma unroll
    for (int i = 0; i < 4; i++) {
        const float* row = xb + ((2 * ph + i) * 128 + 2 * pw) * 3;
        float f[12];
        #pragma unroll
        for (int j = 0; j < 6; j++) {
            float2 t2 = __ldg((const float2*)row + j);
            f[2 * j] = t2.x; f[2 * j + 1] = t2.y;
        }
        #pragma unroll
        for (int kw = 0; kw < 3; kw++)
            #pragma unroll
            for (int c = 0; c < 3; c++)
                xa[i][kw * 3 + c] = pack2(f[kw * 3 + c], f[kw * 3 + c + 3]);
    }

    u32 word = 0;
    #pragma unroll 2
    for (int co = 0; co < 32; co++) {
        const ulonglong2* wr = (const ulonglong2*)(&sw2[co * 28]);
        ull acc0 = 0ull, acc1 = 0ull;
        #pragma unroll
        for (int kp = 0; kp < 13; kp++) {
            ulonglong2 wp = wr[kp];
            const int k0 = 2 * kp, k1 = 2 * kp + 1;
            acc0 = ffma2(wp.x, xa[k0 / 9][k0 % 9], acc0);
            acc1 = ffma2(wp.x, xa[k0 / 9 + 1][k0 % 9], acc1);
            acc0 = ffma2(wp.y, xa[k1 / 9][k1 % 9], acc0);
            acc1 = ffma2(wp.y, xa[k1 / 9 + 1][k1 % 9], acc1);
        }
        ull w26 = sw2[co * 28 + 26];
        acc0 = ffma2(w26, xa[2][8], acc0);
        acc1 = ffma2(w26, xa[3][8], acc1);
        float a0, a1, a2, a3;
        unpack2(a0, a1, acc0);
        unpack2(a2, a3, acc1);
        word |= ((u32)(fmaxf(fmaxf(a0, a1), fmaxf(a2, a3)) >= thr[co])) << co;
    }
    g_act1[idx] = word;
}

// ---------------- layer 2 ----------------
__device__ __forceinline__ int w9f(const u32 (&a)[4][4], const u32 (&w)[9], int dy, int dx) {
    return R9(a[dy][dx] ^ w[0], a[dy][dx + 1] ^ w[1], a[dy][dx + 2] ^ w[2],
              a[dy + 1][dx] ^ w[3], a[dy + 1][dx + 1] ^ w[4], a[dy + 1][dx + 2] ^ w[5],
              a[dy + 2][dx] ^ w[6], a[dy + 2][dx + 1] ^ w[7], a[dy + 2][dx + 2] ^ w[8]);
}
__global__ __launch_bounds__(256) void k_layer2() {
    int gt = blockIdx.x * 256 + threadIdx.x;
    int gw = gt >> 5, lane = gt & 31;
    int seg = gw & 7, bp = gw >> 3;
    int b = bp / 31, ph = bp % 31;
    int pw0 = seg * 4;

    u32 wA[9], wB[9];
    #pragma unroll
    for (int t = 0; t < 9; t++) {
        wA[t] = g_w2b[lane * 9 + t];
        wB[t] = g_w2b[(lane + 32) * 9 + t];
    }
    int4 cA = g_c2[lane], cB = g_c2[lane + 32];
    int pthrA = (288 - cA.x) >> 1, pthrB = (288 - cB.x) >> 1;

    const u32* rbase = g_act1 + b * 3969 + (2 * ph - 1) * 63;
    bool rv0 = (ph > 0), cv0 = (pw0 > 0);

    u32 a[4][4];
    #pragma unroll
    for (int i = 0; i < 4; i++) {
        bool rv = (i > 0) || rv0;
        #pragma unroll
        for (int j = 0; j < 4; j++) {
            bool cv = (j > 0) || cv0;
            a[i][j] = (rv && cv) ? rbase[i * 63 + 2 * pw0 - 1 + j] : 0u;
        }
    }
    int pbase = b * 961 + ph * 31;

    #pragma unroll
    for (int k = 0; k < 4; k++) {
        int pw = pw0 + k;
        if (pw < 31) {
            int PA[4], PB[4];
            #pragma unroll
            for (int dy = 0; dy < 2; dy++)
                #pragma unroll
                for (int dx = 0; dx < 2; dx++) {
                    PA[dy * 2 + dx] = w9f(a, wA, dy, dx);
                    PB[dy * 2 + dx] = w9f(a, wB, dy, dx);
                }
            bool bitA, bitB;
            if (k == 0 && !(rv0 && cv0)) {
                int cTA = rv0 ? 0 : cA.y, cLA = cv0 ? 0 : cA.z, c0A = (!rv0 && !cv0) ? cA.w : 0;
                int cTB = rv0 ? 0 : cB.y, cLB = cv0 ? 0 : cB.z, c0B = (!rv0 && !cv0) ? cB.w : 0;
                bitA = max(max(288 - 2 * PA[0] - (cTA + cLA - c0A), 288 - 2 * PA[1] - cTA),
                           max(288 - 2 * PA[2] - cLA, 288 - 2 * PA[3])) >= cA.x;
                bitB = max(max(288 - 2 * PB[0] - (cTB + cLB - c0B), 288 - 2 * PB[1] - cTB),
                           max(288 - 2 * PB[2] - cLB, 288 - 2 * PB[3])) >= cB.x;
            } else if (!rv0) {
                bitA = max(max(288 - 2 * PA[0] - cA.y, 288 - 2 * PA[1] - cA.y),
                           max(288 - 2 * PA[2], 288 - 2 * PA[3])) >= cA.x;
                bitB = max(max(288 - 2 * PB[0] - cB.y, 288 - 2 * PB[1] - cB.y),
                           max(288 - 2 * PB[2], 288 - 2 * PB[3])) >= cB.x;
            } else {
                bitA = min(min(PA[0], PA[1]), min(PA[2], PA[3])) <= pthrA;
                bitB = min(min(PB[0], PB[1]), min(PB[2], PB[3])) <= pthrB;
            }
            u32 wordA = __ballot_sync(0xffffffffu, bitA);
            u32 wordB = __ballot_sync(0xffffffffu, bitB);
            if (lane == 0) ((uint2*)g_act2)[pbase + pw] = make_uint2(wordA, wordB);

            if (k < 3 && pw < 30) {
                #pragma unroll
                for (int i = 0; i < 4; i++) {
                    bool rv = (i > 0) || rv0;
                    a[i][0] = a[i][2]; a[i][1] = a[i][3];
                    a[i][2] = rv ? rbase[i * 63 + 2 * pw + 3] : 0u;
                    a[i][3] = rv ? rbase[i * 63 + 2 * pw + 4] : 0u;
                }
            }
        }
    }
}

// ---------------- layer 3: writes s8 activations for L4 MMA ----------------------
__global__ __launch_bounds__(256) void k_layer3() {
    int gt = blockIdx.x * 256 + threadIdx.x;
    int gw = gt >> 5, lane = gt & 31;
    int cow = gw & 3;
    int t1 = gw >> 2;
    int seg = t1 & 3, bp = t1 >> 2;
    int b = bp / 15, ph = bp % 15;
    int co = cow * 32 + lane;
    int pw0 = seg * 4;

    uint2 w[9];
    #pragma unroll
    for (int t = 0; t < 9; t++) w[t] = ((const uint2*)g_w3b)[co * 9 + t];
    int4 c = g_c3[co];
    int pthr = (576 - c.x) >> 1;

    const uint2* rbase = (const uint2*)g_act2 + b * 961 + (2 * ph - 1) * 31;
    bool rv0 = (ph > 0), cv0 = (pw0 > 0);
    uint2 z = make_uint2(0u, 0u);

    uint2 a[4][4];
    #pragma unroll
    for (int i = 0; i < 4; i++) {
        bool rv = (i > 0) || rv0;
        #pragma unroll
        for (int j = 0; j < 4; j++) {
            bool cv = (j > 0) || cv0;
            a[i][j] = (rv && cv) ? rbase[i * 31 + 2 * pw0 - 1 + j] : z;
        }
    }
    char* outb = g_act4b + (size_t)(b * 225 + ph * 15) * 128 + co;

    #pragma unroll
    for (int k = 0; k < 4; k++) {
        int pw = pw0 + k;
        if (pw < 15) {
            int P0 = win18<0, 0>(a, w), P1 = win18<0, 1>(a, w);
            int P2 = win18<1, 0>(a, w), P3 = win18<1, 1>(a, w);
            bool bit;
            if (k == 0 && !(rv0 && cv0)) {
                int cT = rv0 ? 0 : c.y, cL = cv0 ? 0 : c.z, c0 = (!rv0 && !cv0) ? c.w : 0;
                bit = max(max(576 - 2 * P0 - (cT + cL - c0), 576 - 2 * P1 - cT),
                          max(576 - 2 * P2 - cL, 576 - 2 * P3)) >= c.x;
            } else if (!rv0) {
                bit = max(max(576 - 2 * P0 - c.y, 576 - 2 * P1 - c.y),
                          max(576 - 2 * P2, 576 - 2 * P3)) >= c.x;
            } else {
                bit = min(min(P0, P1), min(P2, P3)) <= pthr;
            }
            outb[(size_t)pw * 128] = bit ? (char)1 : (char)-1;

            if (k < 3 && pw < 14) {
                #pragma unroll
                for (int i = 0; i < 4; i++) {
                    bool rv = (i > 0) || rv0;
                    a[i][0] = a[i][2]; a[i][1] = a[i][3];
                    a[i][2] = rv ? rbase[i * 31 + 2 * pw + 3] : z;
                    a[i][3] = rv ? rbase[i * 31 + 2 * pw + 4] : z;
                }
            }
        }
    }
}

// ---------------- layer 4: s8 mma.sync im2col GEMM + pool + BN -------------------
// Template NT so acc/meta stay in registers. CTA = image; two instantiations cover
// M rows [0,112) and [112,196).
#define SM_ACT  0
#define SM_D    28928                       // Dbuf after act staging
#define SM_TOT  (28928 + 112 * 264 * 4)     // 147200

template <int NT, int MBASE, int PH0, int NPR>
__global__ __launch_bounds__(512) void k_l4mma(
        const float* __restrict__ m4, const float* __restrict__ v4,
        const float* __restrict__ b4, float* __restrict__ out) {
    extern __shared__ char dsm[];
    char* actS = dsm + SM_ACT;
    int* Dbuf = (int*)(dsm + SM_D);
    int tid = threadIdx.x;
    int warp = tid >> 5, lane = tid & 31;
    int g = lane >> 2, t = lane & 3;
    int b = blockIdx.x;

    // stage activation image (225 x 128 s8 = 28800 B)
    {
        const uint4* src = (const uint4*)(g_act4b + (size_t)b * 28800);
        uint4* dst = (uint4*)actS;
        for (int u = tid; u < 1800; u += 512) dst[u] = src[u];
    }
    __syncthreads();

    // per-warp row metadata: addr | flags (r==0, c==0, valid)
    int meta[NT][2];
    #pragma unroll
    for (int mt = 0; mt < NT; mt++)
        #pragma unroll
        for (int hf = 0; hf < 2; hf++) {
            int p = MBASE + mt * 16 + g + hf * 8;
            bool pv = (p < 196);
            int r = pv ? p / 14 : 0;
            int c = pv ? p % 14 : 0;
            meta[mt][hf] = ((r * 15 + c) * 128 + t * 4)
                         | ((r == 0) ? (1 << 20) : 0)
                         | ((c == 0) ? (1 << 21) : 0)
                         | (pv ? (1 << 22) : 0);
        }

    int acc[NT][2][4];
    #pragma unroll
    for (int mt = 0; mt < NT; mt++)
        #pragma unroll
        for (int n = 0; n < 2; n++)
            #pragma unroll
            for (int q = 0; q < 4; q++) acc[mt][n][q] = 0;

    #pragma unroll 1
    for (int ks = 0; ks < 36; ks++) {
        int tap = ks >> 2, cq = ks & 3;
        int kh = tap / 3, kw = tap % 3;
        int koff = ((kh - 1) * 15 + (kw - 1)) * 128 + cq * 32;
        bool iTop = (kh == 0), iLeft = (kw == 0);

        const uint2* wf = (const uint2*)g_w4f + ((ks * 32 + 2 * warp) * 32 + lane);
        uint2 B0 = __ldg(wf);
        uint2 B1 = __ldg(wf + 32);

        #pragma unroll
        for (int mt = 0; mt < NT; mt++) {
            u32 av[4];
            #pragma unroll
            for (int hf = 0; hf < 2; hf++) {
                int m = meta[mt][hf];
                bool ok = (m & (1 << 22))
                        && !((m & (1 << 20)) && iTop)
                        && !((m & (1 << 21)) && iLeft);
                u32 lo = 0, hi = 0;
                if (ok) {
                    const char* ap = actS + (m & 0xFFFFF) + koff;
                    lo = *(const u32*)ap;
                    hi = *(const u32*)(ap + 16);
                }
                av[hf] = lo;
                av[hf + 2] = hi;
            }
            mma_s8(acc[mt][0], av[0], av[1], av[2], av[3], B0.x, B0.y);
            mma_s8(acc[mt][1], av[0], av[1], av[2], av[3], B1.x, B1.y);
        }
    }
    __syncthreads();   // act staging no longer read; Dbuf writes begin

    #pragma unroll
    for (int mt = 0; mt < NT; mt++)
        #pragma unroll
        for (int n = 0; n < 2; n++) {
            int col = warp * 16 + n * 8 + t * 2;
            int r0 = mt * 16 + g, r1 = r0 + 8;
            Dbuf[r0 * 264 + col] = acc[mt][n][0];
            Dbuf[r0 * 264 + col + 1] = acc[mt][n][1];
            Dbuf[r1 * 264 + col] = acc[mt][n][2];
            Dbuf[r1 * 264 + col + 1] = acc[mt][n][3];
        }
    __syncthreads();

    // pool 2x2 + BN
    int nout = NPR * 7 * 256;
    for (int idx = tid; idx < nout; idx += 512) {
        int co = idx & 255, rest = idx >> 8;
        int pw = rest % 7, lp = rest / 7;
        int ph = PH0 + lp;
        int l = (2 * ph) * 14 + 2 * pw - MBASE;
        int v0 = Dbuf[l * 264 + co], v1 = Dbuf[(l + 1) * 264 + co];
        int v2 = Dbuf[(l + 14) * 264 + co], v3 = Dbuf[(l + 15) * 264 + co];
        int best = max(max(v0, v1), max(v2, v3));
        out[(size_t)(b * 49 + ph * 7 + pw) * 256 + co] =
            ((float)best - __ldg(m4 + co)) * rsqrtf(__ldg(v4 + co) + BN_EPS) + __ldg(b4 + co);
    }
}

// ---------------- launch ----------------
extern "C" void kernel_launch(void* const* d_in, const int* in_sizes, int n_in,
                              void* d_out, int out_size) {
    const float* x  = (const float*)d_in[0];
    const float* w1 = (const float*)d_in[1];
    const float* m1 = (const float*)d_in[2];
    const float* v1 = (const float*)d_in[3];
    const float* b1 = (const float*)d_in[4];
    const float* w2 = (const float*)d_in[5];
    const float* m2 = (const float*)d_in[6];
    const float* v2 = (const float*)d_in[7];
    const float* b2 = (const float*)d_in[8];
    const float* w3 = (const float*)d_in[9];
    const float* m3 = (const float*)d_in[10];
    const float* v3 = (const float*)d_in[11];
    const float* b3 = (const float*)d_in[12];
    const float* w4 = (const float*)d_in[13];
    const float* m4 = (const float*)d_in[14];
    const float* v4 = (const float*)d_in[15];
    const float* b4 = (const float*)d_in[16];
    float* out = (float*)d_out;

    cudaFuncSetAttribute(k_l4mma<7, 0, 0, 4>,
                         cudaFuncAttributeMaxDynamicSharedMemorySize, SM_TOT);
    cudaFuncSetAttribute(k_l4mma<6, 112, 4, 3>,
                         cudaFuncAttributeMaxDynamicSharedMemorySize, SM_TOT);

    k_layer1<<<NB1 + NBP, 256>>>(x, w1, m1, v1, b1, w2, w3, w4, m2, v2, b2, m3, v3, b3);
    k_layer2<<<64 * 31 * 8 * 32 / 256, 256>>>();
    k_layer3<<<64 * 15 * 4 * 4 * 32 / 256, 256>>>();
    k_l4mma<7, 0, 0, 4><<<64, 512, SM_TOT>>>(m4, v4, b4, out);
    k_l4mma<6, 112, 4, 3><<<64, 512, SM_TOT>>>(m4, v4, b4, out);
}

// round 16
// speedup vs baseline: 3.0660x; 1.7738x over previous
#include <cuda_runtime.h>
#include <math.h>

typedef unsigned long long ull;
typedef unsigned u32;

// ---------------- scratch (device globals; no allocation allowed) ----------------
__device__ u32 g_act1[64 * 63 * 63];
__device__ u32 g_act2[64 * 31 * 31 * 2];
__device__ u32 g_act3[64 * 15 * 15 * 4];
__device__ u32 g_w2b[64 * 9];
__device__ u32 g_w3b[128 * 9 * 2];
__device__ u32 g_w4b[256 * 9 * 4];
__device__ int4 g_c2[64];
__device__ int4 g_c3[128];
__device__ int4 g_c4[256];

#define BN_EPS 1e-3f

// ---------------- f32x2 helpers ----------------
__device__ __forceinline__ ull pack2(float lo, float hi) {
    ull r; asm("mov.b64 %0, {%1, %2};" : "=l"(r) : "f"(lo), "f"(hi)); return r;
}
__device__ __forceinline__ void unpack2(float& lo, float& hi, ull v) {
    asm("mov.b64 {%0, %1}, %2;" : "=f"(lo), "=f"(hi) : "l"(v));
}
__device__ __forceinline__ ull ffma2(ull a, ull b, ull c) {
    ull d; asm("fma.rn.f32x2 %0, %1, %2, %3;" : "=l"(d) : "l"(a), "l"(b), "l"(c)); return d;
}

// ---------------- CSA popcount machinery ----------------
__device__ __forceinline__ void CSA(u32& s, u32& c, u32 a, u32 b, u32 d) {
    u32 t = a ^ b;
    s = t ^ d;
    c = (a & b) | (t & d);
}

__device__ __forceinline__ int R9(u32 x0, u32 x1, u32 x2, u32 x3, u32 x4,
                                  u32 x5, u32 x6, u32 x7, u32 x8) {
    u32 s0, c0, s1, c1, s2, c2, s3, c3, s4, c4;
    CSA(s0, c0, x0, x1, x2);
    CSA(s1, c1, x3, x4, x5);
    CSA(s2, c2, x6, x7, x8);
    CSA(s3, c3, s0, s1, s2);
    CSA(s4, c4, c0, c1, c2);
    u32 s5 = s4 ^ c3, c5 = s4 & c3;
    u32 s6 = c4 ^ c5, c6 = c4 & c5;
    return __popc(s3) + 2 * __popc(s5) + 4 * __popc(s6) + 8 * __popc(c6);
}

__device__ __forceinline__ int R18(const u32 x[18]) {
    u32 a0, b0, a1, b1, a2, b2, a3, b3, a4, b4, a5, b5;
    CSA(a0, b0, x[0], x[1], x[2]);
    CSA(a1, b1, x[3], x[4], x[5]);
    CSA(a2, b2, x[6], x[7], x[8]);
    CSA(a3, b3, x[9], x[10], x[11]);
    CSA(a4, b4, x[12], x[13], x[14]);
    CSA(a5, b5, x[15], x[16], x[17]);
    u32 t0, d0, t1, d1;
    CSA(t0, d0, a0, a1, a2);
    CSA(t1, d1, a3, a4, a5);
    u32 u0 = t0 ^ t1, e0 = t0 & t1;
    int P2 = R9(b0, b1, b2, b3, b4, b5, d0, d1, e0);
    return __popc(u0) + 2 * P2;
}

template <int DY, int DX>
__device__ __forceinline__ int win18(const uint2 (&a)[4][4], const uint2 (&w)[9]) {
    u32 x[18];
    #pragma unroll
    for (int kh = 0; kh < 3; kh++)
        #pragma unroll
        for (int kw = 0; kw < 3; kw++) {
            int t = kh * 3 + kw;
            x[2 * t]     = a[DY + kh][DX + kw].x ^ w[t].x;
            x[2 * t + 1] = a[DY + kh][DX + kw].y ^ w[t].y;
        }
    return R18(x);
}

// ---------------- weight sign packing + per-channel constants --------------------
__device__ void do_pack(int i,
                        const float* __restrict__ w2, const float* __restrict__ w3,
                        const float* __restrict__ w4,
                        const float* __restrict__ m2, const float* __restrict__ v2,
                        const float* __restrict__ b2,
                        const float* __restrict__ m3, const float* __restrict__ v3,
                        const float* __restrict__ b3) {
    if (i < 576) {
        int co = i / 9, t = i % 9;
        u32 bits = 0;
        #pragma unroll
        for (int ci = 0; ci < 32; ci++)
            bits |= ((u32)(w2[(t * 32 + ci) * 64 + co] >= 0.f)) << ci;
        g_w2b[co * 9 + t] = bits;
    } else if (i < 576 + 2304) {
        int j = i - 576;
        int co = j / 18, r = j % 18, t = r / 2, wd = r % 2;
        u32 bits = 0;
        #pragma unroll
        for (int k = 0; k < 32; k++) {
            int ci = wd * 32 + k;
            bits |= ((u32)(w3[(t * 64 + ci) * 128 + co] >= 0.f)) << k;
        }
        g_w3b[(co * 9 + t) * 2 + wd] = bits;
    } else if (i < 576 + 2304 + 9216) {
        int j = i - 2880;
        int co = j / 36, r = j % 36, t = r / 4, wd = r % 4;
        u32 bits = 0;
        #pragma unroll
        for (int k = 0; k < 32; k++) {
            int ci = wd * 32 + k;
            bits |= ((u32)(w4[(t * 128 + ci) * 256 + co] >= 0.f)) << k;
        }
        g_w4b[(co * 9 + t) * 4 + wd] = bits;
    } else if (i < 12096 + 64) {
        int co = i - 12096;
        int ct[9];
        #pragma unroll
        for (int t = 0; t < 9; t++) {
            int pc = 0;
            for (int ci = 0; ci < 32; ci++)
                pc += (w2[(t * 32 + ci) * 64 + co] >= 0.f);
            ct[t] = 32 - 2 * pc;
        }
        float thr = m2[co] - b2[co] * sqrtf(v2[co] + BN_EPS);
        g_c2[co] = make_int4((int)ceilf(thr), ct[0] + ct[1] + ct[2],
                             ct[0] + ct[3] + ct[6], ct[0]);
    } else if (i < 12160 + 128) {
        int co = i - 12160;
        int ct[9];
        #pragma unroll
        for (int t = 0; t < 9; t++) {
            int pc = 0;
            for (int ci = 0; ci < 64; ci++)
                pc += (w3[(t * 64 + ci) * 128 + co] >= 0.f);
            ct[t] = 64 - 2 * pc;
        }
        float thr = m3[co] - b3[co] * sqrtf(v3[co] + BN_EPS);
        g_c3[co] = make_int4((int)ceilf(thr), ct[0] + ct[1] + ct[2],
                             ct[0] + ct[3] + ct[6], ct[0]);
    } else if (i < 12288 + 256) {
        int co = i - 12288;
        int ct[9];
        #pragma unroll
        for (int t = 0; t < 9; t++) {
            int pc = 0;
            for (int ci = 0; ci < 128; ci++)
                pc += (w4[(t * 128 + ci) * 256 + co] >= 0.f);
            ct[t] = 128 - 2 * pc;
        }
        g_c4[co] = make_int4(0, ct[0] + ct[1] + ct[2], ct[0] + ct[3] + ct[6], ct[0]);
    }
}

#define NB1 993
#define NBP 50

// ---------------- layer 1 (+pack): fp32 conv + maxpool + BN-sign, FFMA2 ---------
__global__ __launch_bounds__(256) void k_layer1(
        const float* __restrict__ x, const float* __restrict__ w1,
        const float* __restrict__ m1, const float* __restrict__ v1,
        const float* __restrict__ b1,
        const float* __restrict__ w2, const float* __restrict__ w3,
        const float* __restrict__ w4,
        const float* __restrict__ m2, const float* __restrict__ v2,
        const float* __restrict__ b2,
        const float* __restrict__ m3, const float* __restrict__ v3,
        const float* __restrict__ b3) {
    int tid = threadIdx.x;
    if (blockIdx.x >= NB1) {
        int i = (blockIdx.x - NB1) * 256 + tid;
        if (i < 12544) do_pack(i, w2, w3, w4, m2, v2, b2, m3, v3, b3);
        return;
    }
    __shared__ alignas(16) ull sw2[32 * 28];
    __shared__ float thr[32];
    for (int i = tid; i < 864; i += 256) {
        float s = (w1[i] >= 0.f) ? 1.f : -1.f;
        int k = i >> 5, co = i & 31;
        sw2[co * 28 + k] = pack2(s, s);
    }
    if (tid < 32) thr[tid] = m1[tid] - b1[tid] * sqrtf(v1[tid] + BN_EPS);
    __syncthreads();

    int idx = blockIdx.x * 256 + tid;
    if (idx >= 64 * 63 * 63) return;
    int b = idx / 3969;
    int r = idx % 3969;
    int ph = r / 63, pw = r % 63;

    ull xa[4][9];
    const float* xb = x + (size_t)b * 128 * 128 * 3;
    #pragma unroll
    for (int i = 0; i < 4; i++) {
        const float* row = xb + ((2 * ph + i) * 128 + 2 * pw) * 3;
        float f[12];
        #pragma unroll
        for (int j = 0; j < 6; j++) {
            float2 t2 = __ldg((const float2*)row + j);
            f[2 * j] = t2.x; f[2 * j + 1] = t2.y;
        }
        #pragma unroll
        for (int kw = 0; kw < 3; kw++)
            #pragma unroll
            for (int c = 0; c < 3; c++)
                xa[i][kw * 3 + c] = pack2(f[kw * 3 + c], f[kw * 3 + c + 3]);
    }

    u32 word = 0;
    #pragma unroll 4
    for (int co = 0; co < 32; co++) {
        const ulonglong2* wr = (const ulonglong2*)(&sw2[co * 28]);
        ull acc0 = 0ull, acc1 = 0ull;
        #pragma unroll
        for (int kp = 0; kp < 13; kp++) {
            ulonglong2 wp = wr[kp];
            const int k0 = 2 * kp, k1 = 2 * kp + 1;
            acc0 = ffma2(wp.x, xa[k0 / 9][k0 % 9], acc0);
            acc1 = ffma2(wp.x, xa[k0 / 9 + 1][k0 % 9], acc1);
            acc0 = ffma2(wp.y, xa[k1 / 9][k1 % 9], acc0);
            acc1 = ffma2(wp.y, xa[k1 / 9 + 1][k1 % 9], acc1);
        }
        ull w26 = sw2[co * 28 + 26];
        acc0 = ffma2(w26, xa[2][8], acc0);
        acc1 = ffma2(w26, xa[3][8], acc1);

        float a0, a1, a2, a3;
        unpack2(a0, a1, acc0);
        unpack2(a2, a3, acc1);
        float mx = fmaxf(fmaxf(a0, a1), fmaxf(a2, a3));
        word |= ((u32)(mx >= thr[co])) << co;
    }
    g_act1[idx] = word;
}

// ---------------- layer 2: warp = 4-position segment, lane = 2 channels ----------
__device__ __forceinline__ int w9f(const u32 (&a)[4][4], const u32 (&w)[9], int dy, int dx) {
    return R9(a[dy][dx] ^ w[0], a[dy][dx + 1] ^ w[1], a[dy][dx + 2] ^ w[2],
              a[dy + 1][dx] ^ w[3], a[dy + 1][dx + 1] ^ w[4], a[dy + 1][dx + 2] ^ w[5],
              a[dy + 2][dx] ^ w[6], a[dy + 2][dx + 1] ^ w[7], a[dy + 2][dx + 2] ^ w[8]);
}

__global__ __launch_bounds__(256) void k_layer2() {
    int gt = blockIdx.x * 256 + threadIdx.x;
    int gw = gt >> 5, lane = gt & 31;
    int seg = gw & 7;
    int bp = gw >> 3;
    int b = bp / 31, ph = bp % 31;
    int pw0 = seg * 4;

    u32 wA[9], wB[9];
    #pragma unroll
    for (int t = 0; t < 9; t++) {
        wA[t] = g_w2b[lane * 9 + t];
        wB[t] = g_w2b[(lane + 32) * 9 + t];
    }
    int4 cA = g_c2[lane];
    int4 cB = g_c2[lane + 32];
    int pthrA = (288 - cA.x) >> 1;
    int pthrB = (288 - cB.x) >> 1;

    const u32* rbase = g_act1 + b * 3969 + (2 * ph - 1) * 63;
    bool rv0 = (ph > 0), cv0 = (pw0 > 0);

    u32 a[4][4];
    #pragma unroll
    for (int i = 0; i < 4; i++) {
        bool rv = (i > 0) || rv0;
        #pragma unroll
        for (int j = 0; j < 4; j++) {
            bool cv = (j > 0) || cv0;
            a[i][j] = (rv && cv) ? rbase[i * 63 + 2 * pw0 - 1 + j] : 0u;
        }
    }
    int pbase = b * 961 + ph * 31;

    #pragma unroll
    for (int k = 0; k < 4; k++) {
        int pw = pw0 + k;
        if (pw < 31) {
            int PA[4], PB[4];
            #pragma unroll
            for (int dy = 0; dy < 2; dy++)
                #pragma unroll
                for (int dx = 0; dx < 2; dx++) {
                    PA[dy * 2 + dx] = w9f(a, wA, dy, dx);
                    PB[dy * 2 + dx] = w9f(a, wB, dy, dx);
                }
            bool bitA, bitB;
            if (k == 0 && !(rv0 && cv0)) {
                int cTA = rv0 ? 0 : cA.y, cLA = cv0 ? 0 : cA.z, c0A = (!rv0 && !cv0) ? cA.w : 0;
                int cTB = rv0 ? 0 : cB.y, cLB = cv0 ? 0 : cB.z, c0B = (!rv0 && !cv0) ? cB.w : 0;
                bitA = max(max(288 - 2 * PA[0] - (cTA + cLA - c0A), 288 - 2 * PA[1] - cTA),
                           max(288 - 2 * PA[2] - cLA, 288 - 2 * PA[3])) >= cA.x;
                bitB = max(max(288 - 2 * PB[0] - (cTB + cLB - c0B), 288 - 2 * PB[1] - cTB),
                           max(288 - 2 * PB[2] - cLB, 288 - 2 * PB[3])) >= cB.x;
            } else if (!rv0) {
                bitA = max(max(288 - 2 * PA[0] - cA.y, 288 - 2 * PA[1] - cA.y),
                           max(288 - 2 * PA[2], 288 - 2 * PA[3])) >= cA.x;
                bitB = max(max(288 - 2 * PB[0] - cB.y, 288 - 2 * PB[1] - cB.y),
                           max(288 - 2 * PB[2], 288 - 2 * PB[3])) >= cB.x;
            } else {
                bitA = min(min(PA[0], PA[1]), min(PA[2], PA[3])) <= pthrA;
                bitB = min(min(PB[0], PB[1]), min(PB[2], PB[3])) <= pthrB;
            }
            u32 wordA = __ballot_sync(0xffffffffu, bitA);
            u32 wordB = __ballot_sync(0xffffffffu, bitB);
            if (lane == 0) ((uint2*)g_act2)[pbase + pw] = make_uint2(wordA, wordB);

            if (k < 3 && pw < 30) {
                #pragma unroll
                for (int i = 0; i < 4; i++) {
                    bool rv = (i > 0) || rv0;
                    a[i][0] = a[i][2]; a[i][1] = a[i][3];
                    a[i][2] = rv ? rbase[i * 63 + 2 * pw + 3] : 0u;
                    a[i][3] = rv ? rbase[i * 63 + 2 * pw + 4] : 0u;
                }
            }
        }
    }
}

// ---------------- layer 3: warp = (4-position segment, cow) ----------------------
__global__ __launch_bounds__(256) void k_layer3() {
    int gt = blockIdx.x * 256 + threadIdx.x;
    int gw = gt >> 5, lane = gt & 31;
    int cow = gw & 3;
    int t1 = gw >> 2;
    int seg = t1 & 3;
    int bp = t1 >> 2;
    int b = bp / 15, ph = bp % 15;
    int co = cow * 32 + lane;
    int pw0 = seg * 4;

    uint2 w[9];
    #pragma unroll
    for (int t = 0; t < 9; t++) w[t] = ((const uint2*)g_w3b)[co * 9 + t];
    int4 c = g_c3[co];
    int pthr = (576 - c.x) >> 1;

    const uint2* rbase = (const uint2*)g_act2 + b * 961 + (2 * ph - 1) * 31;
    bool rv0 = (ph > 0), cv0 = (pw0 > 0);
    uint2 z = make_uint2(0u, 0u);

    uint2 a[4][4];
    #pragma unroll
    for (int i = 0; i < 4; i++) {
        bool rv = (i > 0) || rv0;
        #pragma unroll
        for (int j = 0; j < 4; j++) {
            bool cv = (j > 0) || cv0;
            a[i][j] = (rv && cv) ? rbase[i * 31 + 2 * pw0 - 1 + j] : z;
        }
    }
    int pbase = b * 225 + ph * 15;

    #pragma unroll
    for (int k = 0; k < 4; k++) {
        int pw = pw0 + k;
        if (pw < 15) {
            int P0 = win18<0, 0>(a, w), P1 = win18<0, 1>(a, w);
            int P2 = win18<1, 0>(a, w), P3 = win18<1, 1>(a, w);
            bool bit;
            if (k == 0 && !(rv0 && cv0)) {
                int cT = rv0 ? 0 : c.y, cL = cv0 ? 0 : c.z, c0 = (!rv0 && !cv0) ? c.w : 0;
                bit = max(max(576 - 2 * P0 - (cT + cL - c0), 576 - 2 * P1 - cT),
                          max(576 - 2 * P2 - cL, 576 - 2 * P3)) >= c.x;
            } else if (!rv0) {
                bit = max(max(576 - 2 * P0 - c.y, 576 - 2 * P1 - c.y),
                          max(576 - 2 * P2, 576 - 2 * P3)) >= c.x;
            } else {
                bit = min(min(P0, P1), min(P2, P3)) <= pthr;
            }
            u32 word = __ballot_sync(0xffffffffu, bit);
            if (lane == 0) g_act3[(pbase + pw) * 4 + cow] = word;

            if (k < 3 && pw < 14) {
                #pragma unroll
                for (int i = 0; i < 4; i++) {
                    bool rv = (i > 0) || rv0;
                    a[i][0] = a[i][2]; a[i][1] = a[i][3];
                    a[i][2] = rv ? rbase[i * 31 + 2 * pw + 3] : z;
                    a[i][3] = rv ? rbase[i * 31 + 2 * pw + 4] : z;
                }
            }
        }
    }
}

// ---------------- layer 4: warp = (2 positions, cow), 2 halves -------------------
__global__ __launch_bounds__(256) void k_layer4(
        const float* __restrict__ m4, const float* __restrict__ v4,
        const float* __restrict__ b4, float* __restrict__ out) {
    int gt = blockIdx.x * 256 + threadIdx.x;
    int gw = gt >> 5, lane = gt & 31;
    int cow = gw & 7;
    int t1 = gw >> 3;
    int pq = t1 & 3;
    int bp = t1 >> 2;
    int b = bp / 7, ph = bp % 7;
    int co = cow * 32 + lane;
    int pw0 = 2 * pq;

    const uint2* act = (const uint2*)g_act3;
    bool rv0 = (ph > 0), cv0 = (pw0 > 0);
    uint2 z = make_uint2(0u, 0u);

    // hoisted row bases (shared across both halves)
    const uint2* rb[4];
    #pragma unroll
    for (int i = 0; i < 4; i++)
        rb[i] = act + (size_t)(b * 225 + (2 * ph - 1 + i) * 15 + 2 * pw0 - 1) * 2;

    int P[4] = {0, 0, 0, 0}, Q[4] = {0, 0, 0, 0};
    #pragma unroll
    for (int h = 0; h < 2; h++) {
        uint2 w[9];
        #pragma unroll
        for (int t = 0; t < 9; t++) w[t] = ((const uint2*)g_w4b)[(co * 9 + t) * 2 + h];

        uint2 a[4][4];
        #pragma unroll
        for (int i = 0; i < 4; i++) {
            bool rv = (i > 0) || rv0;
            #pragma unroll
            for (int j = 0; j < 4; j++) {
                bool cv = (j > 0) || cv0;
                a[i][j] = (rv && cv) ? rb[i][j * 2 + h] : z;
            }
        }
        P[0] += win18<0, 0>(a, w); P[1] += win18<0, 1>(a, w);
        P[2] += win18<1, 0>(a, w); P[3] += win18<1, 1>(a, w);

        if (pw0 < 6) {
            #pragma unroll
            for (int i = 0; i < 4; i++) {
                bool rv = (i > 0) || rv0;
                a[i][0] = a[i][2]; a[i][1] = a[i][3];
                a[i][2] = rv ? rb[i][4 * 2 + h] : z;
                a[i][3] = rv ? rb[i][5 * 2 + h] : z;
            }
            Q[0] += win18<0, 0>(a, w); Q[1] += win18<0, 1>(a, w);
            Q[2] += win18<1, 0>(a, w); Q[3] += win18<1, 1>(a, w);
        }
    }

    float mean = m4[co];
    float rstd = rsqrtf(v4[co] + BN_EPS);
    float beta = b4[co];
    float* outp = out + (b * 49 + ph * 7 + pw0) * 256 + co;
    int4 c = g_c4[co];

    int best0;
    if (rv0 && cv0) {
        best0 = 1152 - 2 * min(min(P[0], P[1]), min(P[2], P[3]));
    } else {
        int cT = rv0 ? 0 : c.y, cL = cv0 ? 0 : c.z, c0 = (!rv0 && !cv0) ? c.w : 0;
        best0 = max(max(1152 - 2 * P[0] - (cT + cL - c0), 1152 - 2 * P[1] - cT),
                    max(1152 - 2 * P[2] - cL, 1152 - 2 * P[3]));
    }
    outp[0] = ((float)best0 - mean) * rstd + beta;

    if (pw0 < 6) {
        int best1;
        if (rv0) {
            best1 = 1152 - 2 * min(min(Q[0], Q[1]), min(Q[2], Q[3]));
        } else {
            best1 = max(max(1152 - 2 * Q[0] - c.y, 1152 - 2 * Q[1] - c.y),
                        max(1152 - 2 * Q[2], 1152 - 2 * Q[3]));
        }
        outp[256] = ((float)best1 - mean) * rstd + beta;
    }
}

// ---------------- launch ----------------
extern "C" void kernel_launch(void* const* d_in, const int* in_sizes, int n_in,
                              void* d_out, int out_size) {
    const float* x  = (const float*)d_in[0];
    const float* w1 = (const float*)d_in[1];
    const float* m1 = (const float*)d_in[2];
    const float* v1 = (const float*)d_in[3];
    const float* b1 = (const float*)d_in[4];
    const float* w2 = (const float*)d_in[5];
    const float* m2 = (const float*)d_in[6];
    const float* v2 = (const float*)d_in[7];
    const float* b2 = (const float*)d_in[8];
    const float* w3 = (const float*)d_in[9];
    const float* m3 = (const float*)d_in[10];
    const float* v3 = (const float*)d_in[11];
    const float* b3 = (const float*)d_in[12];
    const float* w4 = (const float*)d_in[13];
    const float* m4 = (const float*)d_in[14];
    const float* v4 = (const float*)d_in[15];
    const float* b4 = (const float*)d_in[16];
    float* out = (float*)d_out;

    k_layer1<<<NB1 + NBP, 256>>>(x, w1, m1, v1, b1, w2, w3, w4, m2, v2, b2, m3, v3, b3);
    k_layer2<<<64 * 31 * 8 * 32 / 256, 256>>>();
    k_layer3<<<64 * 15 * 4 * 4 * 32 / 256, 256>>>();
    k_layer4<<<64 * 7 * 4 * 8 * 32 / 256, 256>>>(m4, v4, b4, out);
}

// round 17
// speedup vs baseline: 3.0732x; 1.0023x over previous
#include <cuda_runtime.h>
#include <math.h>

typedef unsigned long long ull;
typedef unsigned u32;

// ---------------- scratch (device globals; no allocation allowed) ----------------
__device__ u32 g_act1[64 * 63 * 63];
__device__ u32 g_act2[64 * 31 * 31 * 2];
__device__ u32 g_act3[64 * 15 * 15 * 4];
__device__ u32 g_w2b[64 * 9];
__device__ u32 g_w3b[128 * 9 * 2];
__device__ u32 g_w4b[256 * 9 * 4];
__device__ int4 g_c2[64];
__device__ int4 g_c3[128];
__device__ int4 g_c4[256];

#define BN_EPS 1e-3f

// ---------------- f32x2 helpers ----------------
__device__ __forceinline__ ull pack2(float lo, float hi) {
    ull r; asm("mov.b64 %0, {%1, %2};" : "=l"(r) : "f"(lo), "f"(hi)); return r;
}
__device__ __forceinline__ void unpack2(float& lo, float& hi, ull v) {
    asm("mov.b64 {%0, %1}, %2;" : "=f"(lo), "=f"(hi) : "l"(v));
}
__device__ __forceinline__ ull ffma2(ull a, ull b, ull c) {
    ull d; asm("fma.rn.f32x2 %0, %1, %2, %3;" : "=l"(d) : "l"(a), "l"(b), "l"(c)); return d;
}

// ---------------- CSA popcount machinery ----------------
__device__ __forceinline__ void CSA(u32& s, u32& c, u32 a, u32 b, u32 d) {
    u32 t = a ^ b;
    s = t ^ d;
    c = (a & b) | (t & d);
}

__device__ __forceinline__ int R9(u32 x0, u32 x1, u32 x2, u32 x3, u32 x4,
                                  u32 x5, u32 x6, u32 x7, u32 x8) {
    u32 s0, c0, s1, c1, s2, c2, s3, c3, s4, c4;
    CSA(s0, c0, x0, x1, x2);
    CSA(s1, c1, x3, x4, x5);
    CSA(s2, c2, x6, x7, x8);
    CSA(s3, c3, s0, s1, s2);
    CSA(s4, c4, c0, c1, c2);
    u32 s5 = s4 ^ c3, c5 = s4 & c3;
    u32 s6 = c4 ^ c5, c6 = c4 & c5;
    return __popc(s3) + 2 * __popc(s5) + 4 * __popc(s6) + 8 * __popc(c6);
}

__device__ __forceinline__ int R18(const u32 x[18]) {
    u32 a0, b0, a1, b1, a2, b2, a3, b3, a4, b4, a5, b5;
    CSA(a0, b0, x[0], x[1], x[2]);
    CSA(a1, b1, x[3], x[4], x[5]);
    CSA(a2, b2, x[6], x[7], x[8]);
    CSA(a3, b3, x[9], x[10], x[11]);
    CSA(a4, b4, x[12], x[13], x[14]);
    CSA(a5, b5, x[15], x[16], x[17]);
    u32 t0, d0, t1, d1;
    CSA(t0, d0, a0, a1, a2);
    CSA(t1, d1, a3, a4, a5);
    u32 u0 = t0 ^ t1, e0 = t0 & t1;
    int P2 = R9(b0, b1, b2, b3, b4, b5, d0, d1, e0);
    return __popc(u0) + 2 * P2;
}

template <int DY, int DX>
__device__ __forceinline__ int win18(const uint2 (&a)[4][4], const uint2 (&w)[9]) {
    u32 x[18];
    #pragma unroll
    for (int kh = 0; kh < 3; kh++)
        #pragma unroll
        for (int kw = 0; kw < 3; kw++) {
            int t = kh * 3 + kw;
            x[2 * t]     = a[DY + kh][DX + kw].x ^ w[t].x;
            x[2 * t + 1] = a[DY + kh][DX + kw].y ^ w[t].y;
        }
    return R18(x);
}

// ---------------- weight sign packing + per-channel constants --------------------
__device__ void do_pack(int i,
                        const float* __restrict__ w2, const float* __restrict__ w3,
                        const float* __restrict__ w4,
                        const float* __restrict__ m2, const float* __restrict__ v2,
                        const float* __restrict__ b2,
                        const float* __restrict__ m3, const float* __restrict__ v3,
                        const float* __restrict__ b3) {
    if (i < 576) {
        int co = i / 9, t = i % 9;
        u32 bits = 0;
        #pragma unroll
        for (int ci = 0; ci < 32; ci++)
            bits |= ((u32)(w2[(t * 32 + ci) * 64 + co] >= 0.f)) << ci;
        g_w2b[co * 9 + t] = bits;
    } else if (i < 576 + 2304) {
        int j = i - 576;
        int co = j / 18, r = j % 18, t = r / 2, wd = r % 2;
        u32 bits = 0;
        #pragma unroll
        for (int k = 0; k < 32; k++) {
            int ci = wd * 32 + k;
            bits |= ((u32)(w3[(t * 64 + ci) * 128 + co] >= 0.f)) << k;
        }
        g_w3b[(co * 9 + t) * 2 + wd] = bits;
    } else if (i < 576 + 2304 + 9216) {
        int j = i - 2880;
        int co = j / 36, r = j % 36, t = r / 4, wd = r % 4;
        u32 bits = 0;
        #pragma unroll
        for (int k = 0; k < 32; k++) {
            int ci = wd * 32 + k;
            bits |= ((u32)(w4[(t * 128 + ci) * 256 + co] >= 0.f)) << k;
        }
        g_w4b[(co * 9 + t) * 4 + wd] = bits;
    } else if (i < 12096 + 64) {
        int co = i - 12096;
        int ct[9];
        #pragma unroll
        for (int t = 0; t < 9; t++) {
            int pc = 0;
            for (int ci = 0; ci < 32; ci++)
                pc += (w2[(t * 32 + ci) * 64 + co] >= 0.f);
            ct[t] = 32 - 2 * pc;
        }
        float thr = m2[co] - b2[co] * sqrtf(v2[co] + BN_EPS);
        g_c2[co] = make_int4((int)ceilf(thr), ct[0] + ct[1] + ct[2],
                             ct[0] + ct[3] + ct[6], ct[0]);
    } else if (i < 12160 + 128) {
        int co = i - 12160;
        int ct[9];
        #pragma unroll
        for (int t = 0; t < 9; t++) {
            int pc = 0;
            for (int ci = 0; ci < 64; ci++)
                pc += (w3[(t * 64 + ci) * 128 + co] >= 0.f);
            ct[t] = 64 - 2 * pc;
        }
        float thr = m3[co] - b3[co] * sqrtf(v3[co] + BN_EPS);
        g_c3[co] = make_int4((int)ceilf(thr), ct[0] + ct[1] + ct[2],
                             ct[0] + ct[3] + ct[6], ct[0]);
    } else if (i < 12288 + 256) {
        int co = i - 12288;
        int ct[9];
        #pragma unroll
        for (int t = 0; t < 9; t++) {
            int pc = 0;
            for (int ci = 0; ci < 128; ci++)
                pc += (w4[(t * 128 + ci) * 256 + co] >= 0.f);
            ct[t] = 128 - 2 * pc;
        }
        g_c4[co] = make_int4(0, ct[0] + ct[1] + ct[2], ct[0] + ct[3] + ct[6], ct[0]);
    }
}

#define NB1 993
#define NBP 50

// ---------------- layer 1 (+pack): fp32 conv + maxpool + BN-sign, FFMA2 ---------
__global__ __launch_bounds__(256) void k_layer1(
        const float* __restrict__ x, const float* __restrict__ w1,
        const float* __restrict__ m1, const float* __restrict__ v1,
        const float* __restrict__ b1,
        const float* __restrict__ w2, const float* __restrict__ w3,
        const float* __restrict__ w4,
        const float* __restrict__ m2, const float* __restrict__ v2,
        const float* __restrict__ b2,
        const float* __restrict__ m3, const float* __restrict__ v3,
        const float* __restrict__ b3) {
    int tid = threadIdx.x;
    if (blockIdx.x >= NB1) {
        int i = (blockIdx.x - NB1) * 256 + tid;
        if (i < 12544) do_pack(i, w2, w3, w4, m2, v2, b2, m3, v3, b3);
        return;
    }
    __shared__ alignas(16) ull sw2[32 * 28];
    __shared__ float thr[32];
    for (int i = tid; i < 864; i += 256) {
        float s = (w1[i] >= 0.f) ? 1.f : -1.f;
        int k = i >> 5, co = i & 31;
        sw2[co * 28 + k] = pack2(s, s);
    }
    if (tid < 32) thr[tid] = m1[tid] - b1[tid] * sqrtf(v1[tid] + BN_EPS);
    __syncthreads();

    int idx = blockIdx.x * 256 + tid;
    if (idx >= 64 * 63 * 63) return;
    int b = idx / 3969;
    int r = idx % 3969;
    int ph = r / 63, pw = r % 63;

    ull xa[4][9];
    const float* xb = x + (size_t)b * 128 * 128 * 3;
    #pragma unroll
    for (int i = 0; i < 4; i++) {
        const float* row = xb + ((2 * ph + i) * 128 + 2 * pw) * 3;
        float f[12];
        #pragma unroll
        for (int j = 0; j < 6; j++) {
            float2 t2 = __ldg((const float2*)row + j);
            f[2 * j] = t2.x; f[2 * j + 1] = t2.y;
        }
        #pragma unroll
        for (int kw = 0; kw < 3; kw++)
            #pragma unroll
            for (int c = 0; c < 3; c++)
                xa[i][kw * 3 + c] = pack2(f[kw * 3 + c], f[kw * 3 + c + 3]);
    }

    u32 word = 0;
    #pragma unroll 4
    for (int co = 0; co < 32; co++) {
        const ulonglong2* wr = (const ulonglong2*)(&sw2[co * 28]);
        ull acc0 = 0ull, acc1 = 0ull;
        #pragma unroll
        for (int kp = 0; kp < 13; kp++) {
            ulonglong2 wp = wr[kp];
            const int k0 = 2 * kp, k1 = 2 * kp + 1;
            acc0 = ffma2(wp.x, xa[k0 / 9][k0 % 9], acc0);
            acc1 = ffma2(wp.x, xa[k0 / 9 + 1][k0 % 9], acc1);
            acc0 = ffma2(wp.y, xa[k1 / 9][k1 % 9], acc0);
            acc1 = ffma2(wp.y, xa[k1 / 9 + 1][k1 % 9], acc1);
        }
        ull w26 = sw2[co * 28 + 26];
        acc0 = ffma2(w26, xa[2][8], acc0);
        acc1 = ffma2(w26, xa[3][8], acc1);

        float a0, a1, a2, a3;
        unpack2(a0, a1, acc0);
        unpack2(a2, a3, acc1);
        float mx = fmaxf(fmaxf(a0, a1), fmaxf(a2, a3));
        word |= ((u32)(mx >= thr[co])) << co;
    }
    g_act1[idx] = word;
}

// ---------------- layer 2: warp = 4-position segment, lane = 2 channels ----------
__device__ __forceinline__ int w9f(const u32 (&a)[4][4], const u32 (&w)[9], int dy, int dx) {
    return R9(a[dy][dx] ^ w[0], a[dy][dx + 1] ^ w[1], a[dy][dx + 2] ^ w[2],
              a[dy + 1][dx] ^ w[3], a[dy + 1][dx + 1] ^ w[4], a[dy + 1][dx + 2] ^ w[5],
              a[dy + 2][dx] ^ w[6], a[dy + 2][dx + 1] ^ w[7], a[dy + 2][dx + 2] ^ w[8]);
}

__global__ __launch_bounds__(256) void k_layer2() {
    int gt = blockIdx.x * 256 + threadIdx.x;
    int gw = gt >> 5, lane = gt & 31;
    int seg = gw & 7;
    int bp = gw >> 3;
    int b = bp / 31, ph = bp % 31;
    int pw0 = seg * 4;

    u32 wA[9], wB[9];
    #pragma unroll
    for (int t = 0; t < 9; t++) {
        wA[t] = g_w2b[lane * 9 + t];
        wB[t] = g_w2b[(lane + 32) * 9 + t];
    }
    int4 cA = g_c2[lane];
    int4 cB = g_c2[lane + 32];
    int pthrA = (288 - cA.x) >> 1;
    int pthrB = (288 - cB.x) >> 1;

    const u32* rbase = g_act1 + b * 3969 + (2 * ph - 1) * 63;
    bool rv0 = (ph > 0), cv0 = (pw0 > 0);

    u32 a[4][4];
    #pragma unroll
    for (int i = 0; i < 4; i++) {
        bool rv = (i > 0) || rv0;
        #pragma unroll
        for (int j = 0; j < 4; j++) {
            bool cv = (j > 0) || cv0;
            a[i][j] = (rv && cv) ? rbase[i * 63 + 2 * pw0 - 1 + j] : 0u;
        }
    }
    int pbase = b * 961 + ph * 31;

    #pragma unroll
    for (int k = 0; k < 4; k++) {
        int pw = pw0 + k;
        if (pw < 31) {
            int PA[4], PB[4];
            #pragma unroll
            for (int dy = 0; dy < 2; dy++)
                #pragma unroll
                for (int dx = 0; dx < 2; dx++) {
                    PA[dy * 2 + dx] = w9f(a, wA, dy, dx);
                    PB[dy * 2 + dx] = w9f(a, wB, dy, dx);
                }
            bool bitA, bitB;
            if (k == 0 && !(rv0 && cv0)) {
                int cTA = rv0 ? 0 : cA.y, cLA = cv0 ? 0 : cA.z, c0A = (!rv0 && !cv0) ? cA.w : 0;
                int cTB = rv0 ? 0 : cB.y, cLB = cv0 ? 0 : cB.z, c0B = (!rv0 && !cv0) ? cB.w : 0;
                bitA = max(max(288 - 2 * PA[0] - (cTA + cLA - c0A), 288 - 2 * PA[1] - cTA),
                           max(288 - 2 * PA[2] - cLA, 288 - 2 * PA[3])) >= cA.x;
                bitB = max(max(288 - 2 * PB[0] - (cTB + cLB - c0B), 288 - 2 * PB[1] - cTB),
                           max(288 - 2 * PB[2] - cLB, 288 - 2 * PB[3])) >= cB.x;
            } else if (!rv0) {
                bitA = max(max(288 - 2 * PA[0] - cA.y, 288 - 2 * PA[1] - cA.y),
                           max(288 - 2 * PA[2], 288 - 2 * PA[3])) >= cA.x;
                bitB = max(max(288 - 2 * PB[0] - cB.y, 288 - 2 * PB[1] - cB.y),
                           max(288 - 2 * PB[2], 288 - 2 * PB[3])) >= cB.x;
            } else {
                bitA = min(min(PA[0], PA[1]), min(PA[2], PA[3])) <= pthrA;
                bitB = min(min(PB[0], PB[1]), min(PB[2], PB[3])) <= pthrB;
            }
            u32 wordA = __ballot_sync(0xffffffffu, bitA);
            u32 wordB = __ballot_sync(0xffffffffu, bitB);
            if (lane == 0) ((uint2*)g_act2)[pbase + pw] = make_uint2(wordA, wordB);

            if (k < 3 && pw < 30) {
                #pragma unroll
                for (int i = 0; i < 4; i++) {
                    bool rv = (i > 0) || rv0;
                    a[i][0] = a[i][2]; a[i][1] = a[i][3];
                    a[i][2] = rv ? rbase[i * 63 + 2 * pw + 3] : 0u;
                    a[i][3] = rv ? rbase[i * 63 + 2 * pw + 4] : 0u;
                }
            }
        }
    }
}

// ---------------- layer 3: warp = (4-position segment, cow) ----------------------
__global__ __launch_bounds__(256) void k_layer3() {
    int gt = blockIdx.x * 256 + threadIdx.x;
    int gw = gt >> 5, lane = gt & 31;
    int cow = gw & 3;
    int t1 = gw >> 2;
    int seg = t1 & 3;
    int bp = t1 >> 2;
    int b = bp / 15, ph = bp % 15;
    int co = cow * 32 + lane;
    int pw0 = seg * 4;

    uint2 w[9];
    #pragma unroll
    for (int t = 0; t < 9; t++) w[t] = ((const uint2*)g_w3b)[co * 9 + t];
    int4 c = g_c3[co];
    int pthr = (576 - c.x) >> 1;

    const uint2* rbase = (const uint2*)g_act2 + b * 961 + (2 * ph - 1) * 31;
    bool rv0 = (ph > 0), cv0 = (pw0 > 0);
    uint2 z = make_uint2(0u, 0u);

    uint2 a[4][4];
    #pragma unroll
    for (int i = 0; i < 4; i++) {
        bool rv = (i > 0) || rv0;
        #pragma unroll
        for (int j = 0; j < 4; j++) {
            bool cv = (j > 0) || cv0;
            a[i][j] = (rv && cv) ? rbase[i * 31 + 2 * pw0 - 1 + j] : z;
        }
    }
    int pbase = b * 225 + ph * 15;

    #pragma unroll
    for (int k = 0; k < 4; k++) {
        int pw = pw0 + k;
        if (pw < 15) {
            int P0 = win18<0, 0>(a, w), P1 = win18<0, 1>(a, w);
            int P2 = win18<1, 0>(a, w), P3 = win18<1, 1>(a, w);
            bool bit;
            if (k == 0 && !(rv0 && cv0)) {
                int cT = rv0 ? 0 : c.y, cL = cv0 ? 0 : c.z, c0 = (!rv0 && !cv0) ? c.w : 0;
                bit = max(max(576 - 2 * P0 - (cT + cL - c0), 576 - 2 * P1 - cT),
                          max(576 - 2 * P2 - cL, 576 - 2 * P3)) >= c.x;
            } else if (!rv0) {
                bit = max(max(576 - 2 * P0 - c.y, 576 - 2 * P1 - c.y),
                          max(576 - 2 * P2, 576 - 2 * P3)) >= c.x;
            } else {
                bit = min(min(P0, P1), min(P2, P3)) <= pthr;
            }
            u32 word = __ballot_sync(0xffffffffu, bit);
            if (lane == 0) g_act3[(pbase + pw) * 4 + cow] = word;

            if (k < 3 && pw < 14) {
                #pragma unroll
                for (int i = 0; i < 4; i++) {
                    bool rv = (i > 0) || rv0;
                    a[i][0] = a[i][2]; a[i][1] = a[i][3];
                    a[i][2] = rv ? rbase[i * 31 + 2 * pw + 3] : z;
                    a[i][3] = rv ? rbase[i * 31 + 2 * pw + 4] : z;
                }
            }
        }
    }
}

// ---------------- layer 4: warp = (2 positions, cow), 2 halves (R11 exact) -------
__global__ __launch_bounds__(256) void k_layer4(
        const float* __restrict__ m4, const float* __restrict__ v4,
        const float* __restrict__ b4, float* __restrict__ out) {
    int gt = blockIdx.x * 256 + threadIdx.x;
    int gw = gt >> 5, lane = gt & 31;
    int cow = gw & 7;
    int t1 = gw >> 3;
    int pq = t1 & 3;
    int bp = t1 >> 2;
    int b = bp / 7, ph = bp % 7;
    int co = cow * 32 + lane;
    int pw0 = 2 * pq;

    const uint2* act = (const uint2*)g_act3;
    bool rv0 = (ph > 0), cv0 = (pw0 > 0);
    uint2 z = make_uint2(0u, 0u);

    int P[4] = {0, 0, 0, 0}, Q[4] = {0, 0, 0, 0};
    #pragma unroll
    for (int h = 0; h < 2; h++) {
        uint2 w[9];
        #pragma unroll
        for (int t = 0; t < 9; t++) w[t] = ((const uint2*)g_w4b)[(co * 9 + t) * 2 + h];

        uint2 a[4][4];
        #pragma unroll
        for (int i = 0; i < 4; i++) {
            bool rv = (i > 0) || rv0;
            #pragma unroll
            for (int j = 0; j < 4; j++) {
                bool cv = (j > 0) || cv0;
                int rr = 2 * ph - 1 + i, cc = 2 * pw0 - 1 + j;
                a[i][j] = (rv && cv) ? act[(b * 225 + rr * 15 + cc) * 2 + h] : z;
            }
        }
        P[0] += win18<0, 0>(a, w); P[1] += win18<0, 1>(a, w);
        P[2] += win18<1, 0>(a, w); P[3] += win18<1, 1>(a, w);

        if (pw0 < 6) {
            #pragma unroll
            for (int i = 0; i < 4; i++) {
                bool rv = (i > 0) || rv0;
                int rr = 2 * ph - 1 + i;
                a[i][0] = a[i][2]; a[i][1] = a[i][3];
                a[i][2] = rv ? act[(b * 225 + rr * 15 + 2 * pw0 + 3) * 2 + h] : z;
                a[i][3] = rv ? act[(b * 225 + rr * 15 + 2 * pw0 + 4) * 2 + h] : z;
            }
            Q[0] += win18<0, 0>(a, w); Q[1] += win18<0, 1>(a, w);
            Q[2] += win18<1, 0>(a, w); Q[3] += win18<1, 1>(a, w);
        }
    }

    float mean = m4[co];
    float rstd = rsqrtf(v4[co] + BN_EPS);
    float beta = b4[co];
    float* outp = out + (b * 49 + ph * 7 + pw0) * 256 + co;
    int4 c = g_c4[co];

    int best0;
    if (rv0 && cv0) {
        best0 = 1152 - 2 * min(min(P[0], P[1]), min(P[2], P[3]));
    } else {
        int cT = rv0 ? 0 : c.y, cL = cv0 ? 0 : c.z, c0 = (!rv0 && !cv0) ? c.w : 0;
        best0 = max(max(1152 - 2 * P[0] - (cT + cL - c0), 1152 - 2 * P[1] - cT),
                    max(1152 - 2 * P[2] - cL, 1152 - 2 * P[3]));
    }
    outp[0] = ((float)best0 - mean) * rstd + beta;

    if (pw0 < 6) {
        int best1;
        if (rv0) {
            best1 = 1152 - 2 * min(min(Q[0], Q[1]), min(Q[2], Q[3]));
        } else {
            best1 = max(max(1152 - 2 * Q[0] - c.y, 1152 - 2 * Q[1] - c.y),
                        max(1152 - 2 * Q[2], 1152 - 2 * Q[3]));
        }
        outp[256] = ((float)best1 - mean) * rstd + beta;
    }
}

// ---------------- launch ----------------
extern "C" void kernel_launch(void* const* d_in, const int* in_sizes, int n_in,
                              void* d_out, int out_size) {
    const float* x  = (const float*)d_in[0];
    const float* w1 = (const float*)d_in[1];
    const float* m1 = (const float*)d_in[2];
    const float* v1 = (const float*)d_in[3];
    const float* b1 = (const float*)d_in[4];
    const float* w2 = (const float*)d_in[5];
    const float* m2 = (const float*)d_in[6];
    const float* v2 = (const float*)d_in[7];
    const float* b2 = (const float*)d_in[8];
    const float* w3 = (const float*)d_in[9];
    const float* m3 = (const float*)d_in[10];
    const float* v3 = (const float*)d_in[11];
    const float* b3 = (const float*)d_in[12];
    const float* w4 = (const float*)d_in[13];
    const float* m4 = (const float*)d_in[14];
    const float* v4 = (const float*)d_in[15];
    const float* b4 = (const float*)d_in[16];
    float* out = (float*)d_out;

    k_layer1<<<NB1 + NBP, 256>>>(x, w1, m1, v1, b1, w2, w3, w4, m2, v2, b2, m3, v3, b3);
    k_layer2<<<64 * 31 * 8 * 32 / 256, 256>>>();
    k_layer3<<<64 * 15 * 4 * 4 * 32 / 256, 256>>>();
    k_layer4<<<64 * 7 * 4 * 8 * 32 / 256, 256>>>(m4, v4, b4, out);
}